// round 7
// baseline (speedup 1.0000x reference)
#include <cuda_runtime.h>

// LinearInterpolation specialized for nk=13 knots, m=48 positions.
//   out[b, p, :] = lerp(value[b, seg(p), :], value[b, seg(p)+1, :], t(p))
//
// R7: remove the STG.128 warp-issue tax (12 cyc/warp-op ~= 8.5us/SM floor).
// Outputs are built in smem (STS.128 ~4 cyc) and drained by cp.async.bulk
// (TMA bulk store) which uses no warp issue slots.
// Fixes vs the failed R5 attempt:
//  - THREE output buffers: reuse waits on the bulk store issued 3 tiles ago
//    (bulk_wait_group.read 2) -> fast-path, no stall (R5 waited on the
//    1-tile-old store and stalled every tile)
//  - 3-stage cp.async input pipeline (wait_group 2)
//  - 46KB smem static, 4 blocks/SM, grid 592 persistent

typedef unsigned long long ull;

__device__ __forceinline__ ull fma2(ull a, ull b, ull c) {
    ull d;
    asm("fma.rn.f32x2 %0, %1, %2, %3;" : "=l"(d) : "l"(a), "l"(b), "l"(c));
    return d;
}
__device__ __forceinline__ ull pack2(float lo, float hi) {
    ull d;
    asm("mov.b64 %0, {%1, %2};" : "=l"(d) : "f"(lo), "f"(hi));
    return d;
}
__device__ __forceinline__ void cp16(unsigned s, const void* g) {
    asm volatile("cp.async.cg.shared.global [%0], [%1], 16;" :: "r"(s), "l"(g));
}
__device__ __forceinline__ void cp8(unsigned s, const void* g) {
    asm volatile("cp.async.ca.shared.global [%0], [%1], 8;" :: "r"(s), "l"(g));
}
__device__ __forceinline__ void cp_commit() { asm volatile("cp.async.commit_group;"); }
template <int N>
__device__ __forceinline__ void cp_wait() {
    asm volatile("cp.async.wait_group %0;" :: "n"(N));
}
__device__ __forceinline__ void bulk_store(void* g, unsigned s, unsigned bytes) {
    asm volatile("cp.async.bulk.global.shared::cta.bulk_group [%0], [%1], %2;"
                 :: "l"(g), "r"(s), "r"(bytes) : "memory");
}
__device__ __forceinline__ void bulk_commit() {
    asm volatile("cp.async.bulk.commit_group;" ::: "memory");
}
template <int N>
__device__ __forceinline__ void bulk_wait_read() {
    asm volatile("cp.async.bulk.wait_group.read %0;" :: "n"(N) : "memory");
}
template <int N>
__device__ __forceinline__ void bulk_wait() {
    asm volatile("cp.async.bulk.wait_group %0;" :: "n"(N) : "memory");
}
__device__ __forceinline__ void fence_async_smem() {
    asm volatile("fence.proxy.async.shared::cta;" ::: "memory");
}

// ---- specialized path: nk=13, m=48 ----
#define NK    13
#define FR    26               // floats per input row
#define FR2   13               // float2 (ull) per input row
#define M     48
#define TXc   24               // float4 outputs per row
#define TYc   8
#define NTHREADS (TXc * TYc)   // 192
#define ROWS  32
#define KITER (ROWS / TYc)     // 4
#define IN_STAGES  3
#define OUT_STAGES 3

__global__ __launch_bounds__(NTHREADS)
void lerp_spec_kernel(const int*    __restrict__ index,
                      const float4* __restrict__ v4,
                      float4*       __restrict__ out4,
                      int batch)
{
    __shared__ __align__(16)  float  s_in[IN_STAGES][ROWS * FR];    // 3 x 3328 B
    __shared__ __align__(128) float4 s_out[OUT_STAGES][ROWS * TXc]; // 3 x 12288 B
    __shared__ int   s_seg[M];
    __shared__ float s_t[M];

    const int tx  = threadIdx.x;          // 0..23
    const int ty  = threadIdx.y;          // 0..7
    const int tid = ty * TXc + tx;

    const int nTiles = (batch + ROWS - 1) / ROWS;
    if (blockIdx.x >= nTiles) return;

    // ---- seg / t precompute (once per block) ----
    if (tid < M) {
        const int p = index[0] + 1 + tid;
        int seg = 0;
        #pragma unroll
        for (int i = 1; i < NK; ++i)
            if (index[i] < p) seg = i;
        const float x0 = (float)index[seg];
        const float x1 = (float)index[seg + 1];
        s_seg[tid] = seg;
        s_t[tid]   = ((float)p - x0) / (x1 - x0);
    }

    const float* gin = reinterpret_cast<const float*>(v4);

    auto prefetch = [&](int t, int buf) {
        const int r0      = t * ROWS;
        const int nfloats = min(ROWS, batch - r0) * FR;   // 832 full
        const int nf4     = nfloats >> 2;                 // 208 full
        const float* g    = gin + (long long)r0 * FR;
        unsigned s = (unsigned)__cvta_generic_to_shared(&s_in[buf][0]);
        #pragma unroll
        for (int j = 0; j < 2; ++j) {
            const int i = tid + j * NTHREADS;
            if (i < nf4) cp16(s + i * 16, g + i * 4);
        }
        if (tid == 0 && (nfloats & 3))
            cp8(s + nf4 * 16, g + nf4 * 4);
        cp_commit();
    };

    // ---- prologue: fill input pipeline ----
    int nextTile = blockIdx.x;
    #pragma unroll
    for (int sb = 0; sb < IN_STAGES; ++sb) {
        if (nextTile < nTiles) { prefetch(nextTile, sb); nextTile += gridDim.x; }
        else cp_commit();
    }
    __syncthreads();                      // s_seg / s_t visible

    // ---- per-thread loop invariants ----
    const int  p0   = tx << 1;
    const int  sA   = s_seg[p0];
    const int  sB   = s_seg[p0 + 1];
    const bool same = (sB == sA);         // knot gaps >= 3 => sB in {sA, sA+1}
    const ull  ttA  = pack2(s_t[p0],     s_t[p0]);
    const ull  ttB  = pack2(s_t[p0 + 1], s_t[p0 + 1]);
    const ull  M1   = 0xBF800000BF800000ULL;

    int ci = 0, co = 0;
    for (int tile = blockIdx.x; tile < nTiles; tile += gridDim.x) {
        cp_wait<IN_STAGES - 1>();         // input buf ci ready
        if (tid == 0) bulk_wait_read<OUT_STAGES - 1>();  // out buf co reusable
        __syncthreads();

        const int row0  = tile * ROWS;
        const int nrows = min(ROWS, batch - row0);
        const ull* rb   = reinterpret_cast<const ull*>(&s_in[ci][0]) + ty * FR2;
        float4* ob      = &s_out[co][0];

        #pragma unroll
        for (int k = 0; k < KITER; ++k) {
            const int row = ty + k * TYc;
            if (row >= nrows) break;

            const ull* r = rb + k * (TYc * FR2);
            const ull c0 = r[sA];
            const ull c1 = r[sA + 1];
            const ull c2 = r[sB + 1];
            const ull b0 = same ? c0 : c1;

            const ull oA = fma2(fma2(c0, M1, c1), ttA, c0);
            const ull oB = fma2(fma2(b0, M1, c2), ttB, b0);

            float4 o;
            asm("mov.b64 {%0, %1}, %2;" : "=f"(o.x), "=f"(o.y) : "l"(oA));
            asm("mov.b64 {%0, %1}, %2;" : "=f"(o.z), "=f"(o.w) : "l"(oB));
            ob[row * TXc + tx] = o;       // STS.128, conflict-free
        }
        __syncthreads();                  // all STS for this tile done

        if (tid == 0) {
            fence_async_smem();           // order STS before async-proxy read
            bulk_store(out4 + (long long)row0 * TXc,
                       (unsigned)__cvta_generic_to_shared(&s_out[co][0]),
                       (unsigned)(nrows * TXc * 16));
            bulk_commit();
        }

        if (nextTile < nTiles) { prefetch(nextTile, ci); nextTile += gridDim.x; }
        else cp_commit();                 // keep cp.async group accounting aligned

        ci = (ci + 1 == IN_STAGES)  ? 0 : ci + 1;
        co = (co + 1 == OUT_STAGES) ? 0 : co + 1;
    }

    if (tid == 0) bulk_wait<0>();         // drain all bulk stores before exit
}

// ---- generic fallback (any nk/m, m even) ----
#define GTHREADS 256
__global__ __launch_bounds__(GTHREADS)
void lerp_generic_kernel(const int* __restrict__ index,
                         const float* __restrict__ value,
                         float2* __restrict__ out2,
                         int batch, int nk, int m)
{
    __shared__ int   s_seg[256];
    __shared__ float s_t[256];
    const int tid = threadIdx.x;
    if (tid < m) {
        const int p = index[0] + 1 + tid;
        int seg = 0;
        for (int i = 1; i < nk; ++i)
            if (index[i] < p) seg = i;
        const float x0 = (float)index[seg];
        const float x1 = (float)index[seg + 1];
        s_seg[tid] = seg;
        s_t[tid]   = ((float)p - x0) / (x1 - x0);
    }
    __syncthreads();
    const long long total = (long long)batch * m;
    for (long long i = (long long)blockIdx.x * GTHREADS + tid; i < total;
         i += (long long)gridDim.x * GTHREADS) {
        const int pp = (int)(i % m);
        const long long b = i / m;
        const int seg = s_seg[pp];
        const float t = s_t[pp];
        const float2* r = reinterpret_cast<const float2*>(value) + b * nk;
        const float2 v0 = r[seg], v1 = r[seg + 1];
        float2 o;
        o.x = fmaf(v1.x - v0.x, t, v0.x);
        o.y = fmaf(v1.y - v0.y, t, v0.y);
        out2[i] = o;
    }
}

extern "C" void kernel_launch(void* const* d_in, const int* in_sizes, int n_in,
                              void* d_out, int out_size)
{
    const int*   index = (const int*)d_in[0];
    const float* value = (const float*)d_in[1];

    const int nk    = in_sizes[0];                   // 13
    const int batch = in_sizes[1] / (nk * 2);        // 262144
    const int m     = out_size / (batch * 2);        // 48

    if (nk == NK && m == M) {
        const int nTiles = (batch + ROWS - 1) / ROWS;     // 8192
        const int grid   = nTiles < 592 ? nTiles : 592;   // 4 blocks/SM x 148
        dim3 block(TXc, TYc);
        lerp_spec_kernel<<<grid, block>>>(
            index,
            reinterpret_cast<const float4*>(value),
            reinterpret_cast<float4*>(d_out),
            batch);
    } else {
        const long long total = (long long)batch * m;
        int grid = (int)min((total + GTHREADS - 1) / GTHREADS, (long long)65535 * 8);
        lerp_generic_kernel<<<grid, GTHREADS>>>(
            index, value, reinterpret_cast<float2*>(d_out), batch, nk, m);
    }
}

// round 8
// speedup vs baseline: 1.1556x; 1.1556x over previous
#include <cuda_runtime.h>

// LinearInterpolation specialized for nk=13 knots, m=48 positions.
//   out[b, p, :] = lerp(value[b, seg(p), :], value[b, seg(p)+1, :], t(p))
//
// R8: the kernel is at the chip-wide LTS practical ceiling (~6300 B/cyc,
// path-independent): 134 MB compulsory L2 traffic / 18.6us = 7.2 TB/s, and
// three structurally different kernels (STG vs TMA-store, occ 33% vs 75%)
// all land at 18.4-18.9us. Remaining lever = per-tile fixed overhead:
//  - ROWS=64 tiles (half the barrier/wait/loop cost per byte vs R6's 32)
//  - 3-stage cp.async input pipeline, persistent grid 1480 (10 blocks/SM)
//  - direct STG.128 output (simplest of the cap-equivalent variants)
//  - 3-LDS.64 gather (knot gaps >= 3) + packed fma.rn.f32x2

typedef unsigned long long ull;

__device__ __forceinline__ ull fma2(ull a, ull b, ull c) {
    ull d;
    asm("fma.rn.f32x2 %0, %1, %2, %3;" : "=l"(d) : "l"(a), "l"(b), "l"(c));
    return d;
}
__device__ __forceinline__ ull pack2(float lo, float hi) {
    ull d;
    asm("mov.b64 %0, {%1, %2};" : "=l"(d) : "f"(lo), "f"(hi));
    return d;
}
__device__ __forceinline__ void cp16(unsigned s, const void* g) {
    asm volatile("cp.async.cg.shared.global [%0], [%1], 16;" :: "r"(s), "l"(g));
}
__device__ __forceinline__ void cp8(unsigned s, const void* g) {
    asm volatile("cp.async.ca.shared.global [%0], [%1], 8;" :: "r"(s), "l"(g));
}
__device__ __forceinline__ void cp_commit() { asm volatile("cp.async.commit_group;"); }
template <int N>
__device__ __forceinline__ void cp_wait() {
    asm volatile("cp.async.wait_group %0;" :: "n"(N));
}

// ---- specialized path: nk=13, m=48 ----
#define NK    13
#define FR    26               // floats per input row
#define FR2   13               // float2 (ull) per input row
#define M     48
#define TXc   24               // float4 outputs per row
#define TYc   8
#define NTHREADS (TXc * TYc)   // 192
#define ROWS  64
#define KITER (ROWS / TYc)     // 8
#define STAGES 3

__global__ __launch_bounds__(NTHREADS)
void lerp_spec_kernel(const int*    __restrict__ index,
                      const float4* __restrict__ v4,
                      float4*       __restrict__ out4,
                      int batch)
{
    __shared__ __align__(16) float s_in[STAGES][ROWS * FR];  // 3 x 6656 B
    __shared__ int   s_seg[M];
    __shared__ float s_t[M];

    const int tx  = threadIdx.x;          // 0..23
    const int ty  = threadIdx.y;          // 0..7
    const int tid = ty * TXc + tx;

    const int nTiles = (batch + ROWS - 1) / ROWS;
    if (blockIdx.x >= nTiles) return;     // uniform per block

    // ---- seg / t precompute (once per block) ----
    if (tid < M) {
        const int p = index[0] + 1 + tid;
        int seg = 0;
        #pragma unroll
        for (int i = 1; i < NK; ++i)
            if (index[i] < p) seg = i;
        const float x0 = (float)index[seg];
        const float x1 = (float)index[seg + 1];
        s_seg[tid] = seg;
        s_t[tid]   = ((float)p - x0) / (x1 - x0);
    }

    const float* gin = reinterpret_cast<const float*>(v4);

    // stream tile t's input slab into stage buffer `buf` (one commit group)
    auto prefetch = [&](int t, int buf) {
        const int r0      = t * ROWS;
        const int nfloats = min(ROWS, batch - r0) * FR;   // 1664 full
        const int nf4     = nfloats >> 2;                 // 416 full
        const float* g    = gin + (long long)r0 * FR;
        unsigned s = (unsigned)__cvta_generic_to_shared(&s_in[buf][0]);
        #pragma unroll
        for (int j = 0; j < 3; ++j) {                     // 416/192 <= 3
            const int i = tid + j * NTHREADS;
            if (i < nf4) cp16(s + i * 16, g + i * 4);
        }
        if (tid == 0 && (nfloats & 3))
            cp8(s + nf4 * 16, g + nf4 * 4);
        cp_commit();
    };

    // ---- prologue: fill the pipeline ----
    int nextTile = blockIdx.x;
    #pragma unroll
    for (int sb = 0; sb < STAGES; ++sb) {
        if (nextTile < nTiles) { prefetch(nextTile, sb); nextTile += gridDim.x; }
        else cp_commit();                 // keep group accounting consistent
    }
    __syncthreads();                      // s_seg / s_t visible

    // ---- per-thread loop invariants ----
    const int  p0   = tx << 1;
    const int  sA   = s_seg[p0];
    const int  sB   = s_seg[p0 + 1];
    const bool same = (sB == sA);         // knot gaps >= 3 => sB in {sA, sA+1}
    const ull  ttA  = pack2(s_t[p0],     s_t[p0]);
    const ull  ttB  = pack2(s_t[p0 + 1], s_t[p0 + 1]);
    const ull  M1   = 0xBF800000BF800000ULL;   // (-1.f, -1.f)

    int c = 0;
    for (int tile = blockIdx.x; tile < nTiles; tile += gridDim.x) {
        cp_wait<STAGES - 1>();            // oldest stage (buf c) ready
        __syncthreads();

        const int row0  = tile * ROWS;
        const int nrows = min(ROWS, batch - row0);
        const ull* rb   = reinterpret_cast<const ull*>(&s_in[c][0]) + ty * FR2;
        const long long ob = (long long)(row0 + ty) * TXc + tx;

        #pragma unroll
        for (int k = 0; k < KITER; ++k) {
            const int row = ty + k * TYc;
            if (row >= nrows) break;

            const ull* r = rb + k * (TYc * FR2);
            const ull c0 = r[sA];
            const ull c1 = r[sA + 1];
            const ull c2 = r[sB + 1];
            const ull b0 = same ? c0 : c1;

            const ull oA = fma2(fma2(c0, M1, c1), ttA, c0);
            const ull oB = fma2(fma2(b0, M1, c2), ttB, b0);

            float4 o;
            asm("mov.b64 {%0, %1}, %2;" : "=f"(o.x), "=f"(o.y) : "l"(oA));
            asm("mov.b64 {%0, %1}, %2;" : "=f"(o.z), "=f"(o.w) : "l"(oB));
            out4[ob + (long long)k * (TYc * TXc)] = o;
        }
        __syncthreads();                  // readers of buf c done before refill

        if (nextTile < nTiles) { prefetch(nextTile, c); nextTile += gridDim.x; }
        else cp_commit();                 // keep wait_group accounting aligned
        c = (c + 1 == STAGES) ? 0 : c + 1;
    }
}

// ---- generic fallback (any nk/m, m even) ----
#define GTHREADS 256
__global__ __launch_bounds__(GTHREADS)
void lerp_generic_kernel(const int* __restrict__ index,
                         const float* __restrict__ value,
                         float2* __restrict__ out2,
                         int batch, int nk, int m)
{
    __shared__ int   s_seg[256];
    __shared__ float s_t[256];
    const int tid = threadIdx.x;
    if (tid < m) {
        const int p = index[0] + 1 + tid;
        int seg = 0;
        for (int i = 1; i < nk; ++i)
            if (index[i] < p) seg = i;
        const float x0 = (float)index[seg];
        const float x1 = (float)index[seg + 1];
        s_seg[tid] = seg;
        s_t[tid]   = ((float)p - x0) / (x1 - x0);
    }
    __syncthreads();
    const long long total = (long long)batch * m;
    for (long long i = (long long)blockIdx.x * GTHREADS + tid; i < total;
         i += (long long)gridDim.x * GTHREADS) {
        const int pp = (int)(i % m);
        const long long b = i / m;
        const int seg = s_seg[pp];
        const float t = s_t[pp];
        const float2* r = reinterpret_cast<const float2*>(value) + b * nk;
        const float2 v0 = r[seg], v1 = r[seg + 1];
        float2 o;
        o.x = fmaf(v1.x - v0.x, t, v0.x);
        o.y = fmaf(v1.y - v0.y, t, v0.y);
        out2[i] = o;
    }
}

extern "C" void kernel_launch(void* const* d_in, const int* in_sizes, int n_in,
                              void* d_out, int out_size)
{
    const int*   index = (const int*)d_in[0];
    const float* value = (const float*)d_in[1];

    const int nk    = in_sizes[0];                   // 13
    const int batch = in_sizes[1] / (nk * 2);        // 262144
    const int m     = out_size / (batch * 2);        // 48

    if (nk == NK && m == M) {
        const int nTiles = (batch + ROWS - 1) / ROWS;       // 4096
        const int grid   = nTiles < 1480 ? nTiles : 1480;   // 10 blocks/SM x 148
        dim3 block(TXc, TYc);
        lerp_spec_kernel<<<grid, block>>>(
            index,
            reinterpret_cast<const float4*>(value),
            reinterpret_cast<float4*>(d_out),
            batch);
    } else {
        const long long total = (long long)batch * m;
        int grid = (int)min((total + GTHREADS - 1) / GTHREADS, (long long)65535 * 8);
        lerp_generic_kernel<<<grid, GTHREADS>>>(
            index, value, reinterpret_cast<float2*>(d_out), batch, nk, m);
    }
}